// round 5
// baseline (speedup 1.0000x reference)
#include <cuda_runtime.h>
#include <cuda_bf16.h>

#define FULL 0xffffffffu
#define NEGV -1000000000.0f

// Problem shape (fixed): B=64, N=128, L=32
#define BB    64
#define NN_   128
#define LL    32
#define NN2   (NN_ * NN_)            /* 16384 cells per batch */
#define CELLS (BB * NN2)             /* 1,048,576 cells        */
#define K1_CPW 8                     /* cells per warp in K1   */
#define K1_CPB 64                    /* cells per K1 block     */
#define K1_BLOCKS (CELLS / K1_CPB)   /* 16384                  */
#define PARTS (NN2 / K1_CPB)         /* 256 gold partials per batch */
#define PA 144                       /* A pitch (floats): 16B-aligned rows */
#define PB 129                       /* B pitch: odd -> conflict-free scalar reads */

// ---------------- device scratch (no allocations allowed) ----------------
__device__ float g_pot[CELLS];            // row-major pot[b][i][j] (upper triangle valid)
__device__ float g_goldpart[BB * PARTS];  // per-block gold partial sums
__device__ float g_margin[BB];
__device__ unsigned g_count;              // wrapping completion counter (replay-safe)

// float <-> monotonic u32 key for redux.sync.max.u32
__device__ __forceinline__ unsigned f2key(float x) {
    int i = __float_as_int(x);
    return (unsigned)i ^ ((unsigned)(i >> 31) | 0x80000000u);
}
__device__ __forceinline__ float key2f(unsigned k) {
    unsigned u = (k & 0x80000000u) ? (k ^ 0x80000000u) : ~k;
    return __int_as_float((int)u);
}

// ---------------- K1: pot (row-major, upper tri only) + gold partials ----------------
// One warp per 8 consecutive cells (all in one (b,i) row; lane == label, L==32).
//   d = logit[l] - logit[0];  gold += d[g];  pot = max_l(d + (l==g ? 0 : 1))
// The -1e9 augment on (b,0,len-1,0) is patched in K2.
__global__ void __launch_bounds__(256) k1_pot(const float* __restrict__ logits,
                                              const void* __restrict__ labels) {
    const int warp = threadIdx.x >> 5;
    const int lane = threadIdx.x & 31;

    // labels dtype detection (uniform, deterministic): int64 values lie in [-100,32)
    long long v0 = ((const long long*)labels)[lane];
    const bool lab64 = (__ballot_sync(FULL, v0 >= -100 && v0 < 32) == FULL);

    const int c0 = (blockIdx.x * 8 + warp) * K1_CPW;
    int labv = 0;
    if (lane < K1_CPW) {
        labv = lab64 ? (int)((const long long*)labels)[c0 + lane]
                     : ((const int*)labels)[c0 + lane];
        if (labv < 0) labv = 0;
    }

    // front-batched loads (MLP = 8)
    float x[K1_CPW];
    const float* base = logits + (size_t)c0 * LL;
#pragma unroll
    for (int q = 0; q < K1_CPW; ++q) x[q] = base[q * LL + lane];

    const int ii = (c0 >> 7) & 127;   // all 8 cells share row ii
    const int j0 = c0 & 127;

    float golds = 0.0f, potq = 0.0f;
#pragma unroll
    for (int q = 0; q < K1_CPW; ++q) {
        int   g  = __shfl_sync(FULL, labv, q);
        float m0 = __shfl_sync(FULL, x[q], 0);
        golds += __shfl_sync(FULL, x[q], g) - m0;
        if (j0 + q >= ii) {                       // upper triangle only (warp-uniform)
            float cand = x[q] - m0 + (lane == g ? 0.0f : 1.0f);
            unsigned r = __reduce_max_sync(FULL, f2key(cand));
            if (lane == q) potq = key2f(r);
        }
    }
    if (lane < K1_CPW && j0 + lane >= ii) g_pot[c0 + lane] = potq;  // coalesced 32B

    __shared__ float sh[8];
    if (lane == 0) sh[warp] = golds;      // golds is warp-uniform
    __syncthreads();
    if (threadIdx.x == 0) {
        float s = 0.0f;
#pragma unroll
        for (int t = 0; t < 8; ++t) s += sh[t];   // fixed order -> deterministic
        g_goldpart[blockIdx.x] = s;               // blockIdx = b*PARTS + local
    }
}

// ---------------- K2: per-batch max-plus CKY, dual-array contiguous ----------------
// A[i][k]  = span [i, i+k]           (start-indexed, contiguous in k)
// B[j][c]  = span ending at j, width w', stored at c = 127 - w'
// update:  new(i,w) = pot[i][i+w] + max_{k<w} A[i][k] + B[i+w][128-w+k]
// 1024 threads: i = tid>>3, kg = tid&7. A reads LDS.128 (conflict-free),
// B reads scalar with PB=129 (conflict-free). Garbage entries are NEG -> auto-masked.
__global__ void __launch_bounds__(1024) k2_cky(const float* __restrict__ logits,
                                               const void* __restrict__ labels,
                                               float* __restrict__ out) {
    extern __shared__ float smem[];
    float* A  = smem;                  // 128*144 floats
    float* Bv = smem + NN_ * PA;       // 128*129 + 8 floats (tail pad for OOB float reads)
    __shared__ float red[1024];

    const int b = blockIdx.x;
    const int tid = threadIdx.x;

    long long v = ((const long long*)labels)[tid & 31];
    const bool lab64 = (__ballot_sync(FULL, v >= -100 && v < 32) == FULL);

    // sequence length = count(labels[b,0,:] != -100)
    int pflag = 0;
    if (tid < NN_) {
        size_t idx = ((size_t)b << 14) + tid;
        int lab = lab64 ? (int)((const long long*)labels)[idx]
                        : ((const int*)labels)[idx];
        pflag = (lab != -100);
    }
    const int len = __syncthreads_count(pflag);

    // gold partials -> fixed-order tree reduce (deterministic)
    red[tid] = (tid < PARTS) ? g_goldpart[b * PARTS + tid] : 0.0f;
    __syncthreads();
#pragma unroll
    for (int s = 512; s > 0; s >>= 1) {
        if (tid < s) red[tid] += red[tid + s];
        __syncthreads();
    }

    // patch pot[b,0,len-1] with the extra -1e9 augment on label 0
    if (tid < 32) {
        const int j = len - 1;
        size_t cell = ((size_t)b << 14) + j;
        int g = lab64 ? (int)((const long long*)labels)[cell]
                      : ((const int*)labels)[cell];
        if (g < 0) g = 0;
        float x  = logits[cell * LL + tid];
        float m0 = __shfl_sync(FULL, x, 0);
        float cand = (x - m0) + (tid == g ? 0.0f : 1.0f)
                              + (tid == 0 ? NEGV : 0.0f);
#pragma unroll
        for (int o = 16; o > 0; o >>= 1)
            cand = fmaxf(cand, __shfl_xor_sync(FULL, cand, o));
        if (tid == 0) g_pot[cell] = cand;          // row (i=0), col j
    }

    // init A/B to NEG (masking sentinel), then terms
    for (int t = tid; t < NN_ * PA; t += 1024) A[t]  = NEGV;
    for (int t = tid; t < NN_ * PB + 8; t += 1024) Bv[t] = NEGV;
    __syncthreads();   // also makes the g_pot patch visible block-wide

    const float* potb = g_pot + ((size_t)b << 14);
    if (tid < NN_) {
        float tv = potb[tid * (NN_ + 1)];          // pot[i][i] (patched if len==1)
        A[tid * PA]          = tv;                 // A[i][0]
        Bv[tid * PB + 127]   = tv;                 // B[i][127] (width 0)
    }
    __syncthreads();

    const int i  = tid >> 3;
    const int kg = tid & 7;
    const float* Arow = A + i * PA;

    for (int w = 1; w < NN_; ++w) {
        const bool act = (i < NN_ - w);
        float potv = 0.0f;
        if (act) potv = __ldg(potb + i * NN_ + i + w);   // hoisted: L2 hit hidden by loop
        float acc0 = -1e30f, acc1 = -1e30f;
        if (act) {
            const float* bp = Bv + (i + w) * PB + (NN_ - w);
#pragma unroll 2
            for (int k0 = 4 * kg; k0 < w; k0 += 32) {
                float4 a = *(const float4*)(Arow + k0);  // k>=w entries are NEG
                const float* bb = bp + k0;
                acc0 = fmaxf(acc0, a.x + bb[0]);
                acc1 = fmaxf(acc1, a.y + bb[1]);
                acc0 = fmaxf(acc0, a.z + bb[2]);
                acc1 = fmaxf(acc1, a.w + bb[3]);
            }
        }
        float m = fmaxf(acc0, acc1);
        m = fmaxf(m, __shfl_xor_sync(FULL, m, 4));
        m = fmaxf(m, __shfl_xor_sync(FULL, m, 2));
        m = fmaxf(m, __shfl_xor_sync(FULL, m, 1));
        if (act && kg == 0) {
            float nv = m + potv;
            A[i * PA + w]              = nv;       // A[i][w]
            Bv[(i + w) * PB + 127 - w] = nv;       // B[i+w][127-w]
        }
        __syncthreads();
    }

    if (tid == 0) {
        float pred = A[len - 1];                   // span [0, len-1]
        g_margin[b] = fmaxf(pred - red[0], 0.0f);
        __threadfence();
        unsigned old = atomicInc(&g_count, BB - 1);  // wraps -> replay/graph-safe
        if (old == BB - 1) {                         // last block: fixed-order mean
            float s = 0.0f;
            volatile float* gm = g_margin;
#pragma unroll
            for (int t = 0; t < BB; ++t) s += gm[t];
            out[0] = s * (1.0f / (float)BB);
        }
    }
}

// ---------------- launch ----------------
extern "C" void kernel_launch(void* const* d_in, const int* in_sizes, int n_in,
                              void* d_out, int out_size) {
    const float* logits = (const float*)d_in[0];
    const void*  labels = d_in[1];

    const int smem_bytes = (NN_ * PA + NN_ * PB + 8) * (int)sizeof(float); // 139,808
    cudaFuncSetAttribute(k2_cky, cudaFuncAttributeMaxDynamicSharedMemorySize, smem_bytes);

    k1_pot<<<K1_BLOCKS, 256>>>(logits, labels);
    k2_cky<<<BB, 1024, smem_bytes>>>(logits, labels, (float*)d_out);
}